// round 13
// baseline (speedup 1.0000x reference)
#include <cuda_runtime.h>
#include <math.h>
#include <stdint.h>

#define T  1024
#define HD 256
#define NT (T/64)    // 16 row tiles of 64 (mask granularity)
#define NR 32        // 32 row tiles of 32 (gemm granularity)
#define NH (HD/64)   // 4 col tiles

#define NW   33      // 1025 bits per weight bitset

// ---------------- scratch (static device arrays, allowed) ---------------------
__device__ float    g_k[T*HD];
__device__ float    g_q[T*HD];
__device__ float    g_v[T*HD];
__device__ float    g_skip[T*HD];
__device__ float    g_out[T*HD];
__device__ float    g_attn[T*T];
__device__ uint32_t g_res[1056*NW];     // rows 1..1024 used (final scan bitsets)
__device__ uint32_t g_tileact[NT];
__device__ float    g_kpart[4*T];       // per-coltile partial rowsums of k
__device__ float    g_qpart[4*T];       // per-coltile partial rowsums of q

// ==== exact jax.lax.associative_scan emulation, smem up-sweep + reg walk-down ==
#define SCAN_SMEM (1023*NW*4)
__global__ __launch_bounds__(1024) void scan_kernel(const int* __restrict__ start,
                                                    const int* __restrict__ done) {
    extern __shared__ uint32_t s_nodes[];
    const int tid = threadIdx.x;

    // level 1: 512 nodes from leaf pairs (2i, 2i+1); leaves are basis vectors
    for (int i = tid; i < 512; i += 1024) {
        uint32_t* o = &s_nodes[i * NW];
        int gb = 2*i + 1;
        bool sm = start[gb] != 0, dm = done[gb] != 0;
        #pragma unroll
        for (int wd = 0; wd < NW; wd++) o[wd] = 0;
        if (sm) o[(2*i) >> 5] |= 1u << ((2*i) & 31);
        if (dm) o[gb >> 5]    |= 1u << (gb & 31);
    }
    __syncthreads();

    // levels 2..10
    for (int d = 2; d <= 10; d++) {
        int nd   = 1024 >> d;
        int offc = 1024 - (2048 >> (d-1));
        int offo = 1024 - (2048 >> d);
        for (int i = tid; i < nd; i += 1024) {
            const uint32_t* a = &s_nodes[(offc + 2*i    ) * NW];
            const uint32_t* b = &s_nodes[(offc + 2*i + 1) * NW];
            int gb = ((2*i + 2) << (d-1)) - 1;
            uint32_t sm = start[gb] ? 0xFFFFFFFFu : 0u;
            uint32_t dm = done[gb]  ? 0xFFFFFFFFu : 0u;
            uint32_t* o = &s_nodes[(offo + i) * NW];
            #pragma unroll
            for (int wd = 0; wd < NW; wd++) o[wd] = (a[wd] & sm) | (b[wd] & dm);
        }
        __syncthreads();
    }

    // per-thread walk-down for row p = tid+1
    const int p = tid + 1;
    uint32_t acc[NW];
    int pushD[11], pushJ[11];
    int np = 0, d = 0, j = p;
    while (j != 0) {
        if (j & 1) { j = (j - 1) >> 1; d++; }
        else       { pushD[np] = d; pushJ[np] = j; np++; j = (j >> 1) - 1; d++; }
    }
    {
        int offb = 1024 - (2048 >> d);
        const uint32_t* b = &s_nodes[offb * NW];
        #pragma unroll
        for (int wd = 0; wd < NW; wd++) acc[wd] = b[wd];
    }
    for (int i = np - 1; i >= 0; i--) {
        int dd = pushD[i], jj = pushJ[i];
        int gb = (dd == 0) ? jj : (((jj + 1) << dd) - 1);
        uint32_t sm = start[gb] ? 0xFFFFFFFFu : 0u;
        uint32_t dm = done[gb]  ? 0xFFFFFFFFu : 0u;
        if (dd == 0) {                       // node = basis(jj)
            #pragma unroll
            for (int wd = 0; wd < NW; wd++) acc[wd] &= sm;
            if (dm) acc[jj >> 5] |= 1u << (jj & 31);
        } else {
            int offn = 1024 - (2048 >> dd);
            const uint32_t* b = &s_nodes[(offn + jj) * NW];
            #pragma unroll
            for (int wd = 0; wd < NW; wd++) acc[wd] = (acc[wd] & sm) | (b[wd] & dm);
        }
    }
    #pragma unroll
    for (int wd = 0; wd < NW; wd++) g_res[p * NW + wd] = acc[wd];

    // tileact from in-register row
    __shared__ uint32_t sh_act[NT];
    if (tid < NT) sh_act[tid] = 0;
    __syncthreads();
    uint32_t mybits = 0;
    #pragma unroll
    for (int ct = 0; ct < 16; ct++) {
        uint32_t any = (acc[2*ct] & 0xFFFFFFFEu) | acc[2*ct + 1] | (acc[2*ct + 2] & 1u);
        if (any) mybits |= 1u << ct;
    }
    #pragma unroll
    for (int o = 16; o; o >>= 1) mybits |= __shfl_xor_sync(0xffffffffu, mybits, o);
    if ((tid & 31) == 0) atomicOr(&sh_act[tid >> 6], mybits);
    __syncthreads();
    if (tid < NT) g_tileact[tid] = sh_act[tid];
}

// ====== 32x64 double-buffered GEMM core =======================================
#define DB_GEMM(AEXPR, BEXPR)                                                  \
    {                                                                          \
        {   int k0 = 0;                                                        \
            _Pragma("unroll")                                                  \
            for (int l = 0; l < 2; l++) { int e = tid + l*256;                 \
                int kk = e & 15, r = e >> 4; As[0][kk][r] = (AEXPR); }         \
            _Pragma("unroll")                                                  \
            for (int l = 0; l < 4; l++) { int e = tid + l*256;                 \
                int kk = e & 15, c = e >> 4; Bs[0][kk][c] = (BEXPR); }         \
        }                                                                      \
        __syncthreads();                                                       \
        _Pragma("unroll")                                                      \
        for (int ch = 0; ch < 16; ch++) {                                      \
            const int cur = ch & 1;                                            \
            float pa[2], pb[4];                                                \
            if (ch < 15) { int k0 = (ch + 1) * 16;                             \
                _Pragma("unroll")                                              \
                for (int l = 0; l < 2; l++) { int e = tid + l*256;             \
                    int kk = e & 15, r = e >> 4; pa[l] = (AEXPR); }            \
                _Pragma("unroll")                                              \
                for (int l = 0; l < 4; l++) { int e = tid + l*256;             \
                    int kk = e & 15, c = e >> 4; pb[l] = (BEXPR); }            \
            }                                                                  \
            _Pragma("unroll")                                                  \
            for (int kk = 0; kk < 16; kk++) {                                  \
                float a0 = As[cur][kk][ty*2], a1 = As[cur][kk][ty*2+1];        \
                float4 b4 = *(const float4*)&Bs[cur][kk][tx*4];                \
                float b[4] = {b4.x, b4.y, b4.z, b4.w};                         \
                _Pragma("unroll")                                              \
                for (int jj = 0; jj < 4; jj++) {                               \
                    acc[0][jj] = fmaf(a0, b[jj], acc[0][jj]);                  \
                    acc[1][jj] = fmaf(a1, b[jj], acc[1][jj]);                  \
                }                                                              \
            }                                                                  \
            if (ch < 15) { const int nxt = cur ^ 1;                            \
                _Pragma("unroll")                                              \
                for (int l = 0; l < 2; l++) { int e = tid + l*256;             \
                    int kk = e & 15, r = e >> 4; As[nxt][kk][r] = pa[l]; }     \
                _Pragma("unroll")                                              \
                for (int l = 0; l < 4; l++) { int e = tid + l*256;             \
                    int kk = e & 15, c = e >> 4; Bs[nxt][kk][c] = pb[l]; }     \
            }                                                                  \
            __syncthreads();                                                   \
        }                                                                      \
    }

// ---- fused QKV+skip projections; k/q also emit per-coltile partial rowsums ---
__global__ __launch_bounds__(256) void proj_kernel(const float* __restrict__ x,
                                                   const float* __restrict__ Wk,
                                                   const float* __restrict__ Wq,
                                                   const float* __restrict__ Wv,
                                                   const float* __restrict__ Wsk,
                                                   const float* __restrict__ bsk) {
    __shared__ float As[2][16][36];
    __shared__ float Bs[2][16][68];
    const int z = blockIdx.z;
    const float* B = (z == 0) ? Wk : (z == 1) ? Wq : (z == 2) ? Wv : Wsk;
    float* C = (z == 0) ? g_k : (z == 1) ? g_q : (z == 2) ? g_v : g_skip;
    const int row0 = blockIdx.x * 32, col0 = blockIdx.y * 64;
    const int tid = threadIdx.x, tx = tid & 15, ty = tid >> 4;
    float acc[2][4] = {};
    DB_GEMM(x[(row0 + r) * HD + k0 + kk], B[(col0 + c) * HD + k0 + kk]);
    float* part = (z == 0) ? g_kpart : g_qpart;
    #pragma unroll
    for (int i = 0; i < 2; i++) {
        int gi = row0 + ty * 2 + i;
        float rs = 0.f;
        #pragma unroll
        for (int j = 0; j < 4; j++) {
            int gj = col0 + tx * 4 + j;
            float v = acc[i][j];
            if (z == 3) v += bsk[gj];
            if (z <= 1) v = v > 0.f ? v : (expf(v) - 1.f);   // ELU for k,q
            C[gi * HD + gj] = v;
            rs += v;
        }
        if (z <= 1) {       // reduce over the 16 tx lanes (within half-warp)
            #pragma unroll
            for (int o = 1; o < 16; o <<= 1)
                rs += __shfl_xor_sync(0xffffffffu, rs, o);
            if (tx == 0) part[blockIdx.y * T + gi] = rs;
        }
    }
}

// ---------------- masked score tiles (32 rows x 64 cols) ----------------------
__global__ __launch_bounds__(256) void attn_kernel() {
    const int ct = blockIdx.x, rt32 = blockIdx.y;
    if (!((g_tileact[rt32 >> 1] >> ct) & 1)) return;
    __shared__ float As[2][16][36];
    __shared__ float Bs[2][16][68];
    const int row0 = rt32 * 32, col0 = ct * 64;
    const int tid = threadIdx.x, tx = tid & 15, ty = tid >> 4;
    float acc[2][4] = {};
    DB_GEMM(g_q[(row0 + r) * HD + k0 + kk], g_k[(col0 + c) * HD + k0 + kk]);
    #pragma unroll
    for (int i = 0; i < 2; i++) {
        int gi = row0 + ty * 2 + i;
        const uint32_t* wrow = &g_res[(gi + 1) * NW];
        #pragma unroll
        for (int j = 0; j < 4; j++) {
            int pos = col0 + tx * 4 + j + 1;     // leaf index u+1
            float m = ((wrow[pos >> 5] >> (pos & 31)) & 1u) ? 1.f : 0.f;
            g_attn[gi * T + pos - 1] = acc[i][j] * m;
        }
    }
}

// ---- av: inline denom + numer = scores @ V; out = numer * invden -------------
__global__ __launch_bounds__(256) void av_kernel() {
    __shared__ float As[16][36];
    __shared__ float Bs[16][68];
    __shared__ float s_inv[32];
    const int rt32 = blockIdx.x, row0 = rt32 * 32, col0 = blockIdx.y * 64;
    const int tid = threadIdx.x, tx = tid & 15, ty = tid >> 4;
    const uint32_t act = g_tileact[rt32 >> 1];

    // denom phase: warp w does rows {w, w+8, w+16, w+24}
    {
        const int w = tid >> 5, lane = tid & 31;
        #pragma unroll
        for (int rr = 0; rr < 4; rr++) {
            int r = w + rr * 8;
            const uint32_t* wrow = &g_res[(row0 + r + 1) * NW];
            float zs = 0.f;
            for (int wd = lane; wd < NW; wd += 32) {
                uint32_t word = wrow[wd];
                if (wd == 0) word &= 0xFFFFFFFEu;   // leaf 0 = zeros
                while (word) {
                    int b = __ffs(word) - 1;
                    word &= word - 1;
                    int u = wd * 32 + b - 1;
                    zs += g_kpart[u] + g_kpart[T + u] + g_kpart[2*T + u] + g_kpart[3*T + u];
                }
            }
            #pragma unroll
            for (int o = 16; o; o >>= 1) zs += __shfl_xor_sync(0xffffffffu, zs, o);
            if (lane == 0) {
                int gr = row0 + r;
                float qs = g_qpart[gr] + g_qpart[T + gr] + g_qpart[2*T + gr] + g_qpart[3*T + gr];
                s_inv[r] = 1.f / fmaxf(qs * zs, 1e-5f);
            }
        }
    }
    __syncthreads();

    float acc[2][4] = {};
    for (int ut = 0; ut < NT; ut++) {
        if (!((act >> ut) & 1)) continue;
        const int u0 = ut * 64;
        for (int us = 0; us < 64; us += 16) {
            #pragma unroll
            for (int l = 0; l < 2; l++) {
                int e = tid + l * 256;
                int kk = e & 15, r = e >> 4;
                As[kk][r] = g_attn[(row0 + r) * T + u0 + us + kk];
            }
            #pragma unroll
            for (int l = 0; l < 4; l++) {
                int e = tid + l * 256;
                int kk = e & 15, c = e >> 4;
                Bs[kk][c] = g_v[(u0 + us + kk) * HD + col0 + c];
            }
            __syncthreads();
            #pragma unroll
            for (int kk = 0; kk < 16; kk++) {
                float a0 = As[kk][ty * 2], a1 = As[kk][ty * 2 + 1];
                float4 b4 = *(const float4*)&Bs[kk][tx * 4];
                float b[4] = {b4.x, b4.y, b4.z, b4.w};
                #pragma unroll
                for (int j = 0; j < 4; j++) {
                    acc[0][j] = fmaf(a0, b[j], acc[0][j]);
                    acc[1][j] = fmaf(a1, b[j], acc[1][j]);
                }
            }
            __syncthreads();
        }
    }
    #pragma unroll
    for (int i = 0; i < 2; i++) {
        int lr = ty * 2 + i;
        float inv = s_inv[lr];
        #pragma unroll
        for (int j = 0; j < 4; j++)
            g_out[(row0 + lr) * HD + col0 + tx * 4 + j] = acc[i][j] * inv;
    }
}

// ==== fused MLP (3 GEMMs) + LayerNorm; block = 8-row strip, 128 blocks ========
// COALESCED weight staging: thread e loads W[c*256 + kt*16 + kk], kk=e&15, c=e>>4
// (consecutive lanes -> consecutive floats). Ws padded to 264 for float4 align.
__device__ __forceinline__ void mlp_phase(const float* __restrict__ W,
                                          float (*SRC)[256],
                                          float acc[2][4],
                                          float (*Ws)[264],
                                          int tid, int tx, int ty) {
    acc[0][0]=acc[0][1]=acc[0][2]=acc[0][3]=0.f;
    acc[1][0]=acc[1][1]=acc[1][2]=acc[1][3]=0.f;
    float pw[16];
    #pragma unroll
    for (int l = 0; l < 16; l++) {
        int e = tid + l * 256;
        int kk = e & 15, c = e >> 4;
        pw[l] = W[c * 256 + kk];
    }
    for (int kt = 0; kt < 16; kt++) {
        #pragma unroll
        for (int l = 0; l < 16; l++) {
            int e = tid + l * 256;
            int kk = e & 15, c = e >> 4;
            Ws[kk][c] = pw[l];
        }
        __syncthreads();
        if (kt < 15) {
            #pragma unroll
            for (int l = 0; l < 16; l++) {
                int e = tid + l * 256;
                int kk = e & 15, c = e >> 4;
                pw[l] = W[c * 256 + (kt + 1) * 16 + kk];
            }
        }
        #pragma unroll
        for (int kk = 0; kk < 16; kk++) {
            int k = kt * 16 + kk;
            float a0 = SRC[ty * 2][k], a1 = SRC[ty * 2 + 1][k];
            float4 w4 = *(const float4*)&Ws[kk][tx * 4];
            float w[4] = {w4.x, w4.y, w4.z, w4.w};
            #pragma unroll
            for (int j = 0; j < 4; j++) {
                acc[0][j] = fmaf(a0, w[j], acc[0][j]);
                acc[1][j] = fmaf(a1, w[j], acc[1][j]);
            }
        }
        __syncthreads();
    }
}

__global__ __launch_bounds__(256) void mlp_kernel(const float* __restrict__ W1,
                                                  const float* __restrict__ b1,
                                                  const float* __restrict__ W2,
                                                  const float* __restrict__ b2,
                                                  const float* __restrict__ W3,
                                                  const float* __restrict__ b3,
                                                  const float* __restrict__ lnw,
                                                  const float* __restrict__ lnb,
                                                  float* __restrict__ outp) {
    __shared__ float A[8][256];
    __shared__ float Bb[8][256];
    __shared__ float Ws[16][264];
    const int row0 = blockIdx.x * 8;
    const int tid = threadIdx.x, tx = tid & 63, ty = tid >> 6;
    float acc[2][4];

    // load 'out' strip (coalesced)
    #pragma unroll
    for (int l = 0; l < 8; l++) {
        int e = tid + l * 256;
        A[e >> 8][e & 255] = g_out[row0 * HD + e];
    }
    __syncthreads();

    // h1 = mish(out @ W1^T + b1)  : A -> Bb
    mlp_phase(W1, A, acc, Ws, tid, tx, ty);
    #pragma unroll
    for (int i = 0; i < 2; i++)
        #pragma unroll
        for (int j = 0; j < 4; j++) {
            int c = tx * 4 + j;
            float v = acc[i][j] + b1[c];
            float sp = v > 20.f ? v : log1pf(expf(v));
            Bb[ty * 2 + i][c] = v * tanhf(sp);
        }
    __syncthreads();

    // h2 = mish(h1 @ W2^T + b2)  : Bb -> A
    mlp_phase(W2, Bb, acc, Ws, tid, tx, ty);
    #pragma unroll
    for (int i = 0; i < 2; i++)
        #pragma unroll
        for (int j = 0; j < 4; j++) {
            int c = tx * 4 + j;
            float v = acc[i][j] + b2[c];
            float sp = v > 20.f ? v : log1pf(expf(v));
            A[ty * 2 + i][c] = v * tanhf(sp);
        }
    __syncthreads();

    // h3 = h2 @ W3^T + b3 + skip : A -> Bb
    mlp_phase(W3, A, acc, Ws, tid, tx, ty);
    #pragma unroll
    for (int i = 0; i < 2; i++) {
        int r = ty * 2 + i;
        #pragma unroll
        for (int j = 0; j < 4; j++) {
            int c = tx * 4 + j;
            Bb[r][c] = acc[i][j] + b3[c] + g_skip[(row0 + r) * HD + c];
        }
    }
    __syncthreads();

    // layernorm: warp w handles row w
    const int w = tid >> 5, lane = tid & 31;
    float vals[8];
    float s = 0.f;
    #pragma unroll
    for (int i = 0; i < 8; i++) { vals[i] = Bb[w][lane + i * 32]; s += vals[i]; }
    #pragma unroll
    for (int o = 16; o; o >>= 1) s += __shfl_xor_sync(0xffffffffu, s, o);
    float mu = s * (1.f / HD);
    float sq = 0.f;
    #pragma unroll
    for (int i = 0; i < 8; i++) { float d = vals[i] - mu; sq += d * d; }
    #pragma unroll
    for (int o = 16; o; o >>= 1) sq += __shfl_xor_sync(0xffffffffu, sq, o);
    float rstd = rsqrtf(sq * (1.f / HD) + 1e-5f);
    #pragma unroll
    for (int i = 0; i < 8; i++) {
        int c = lane + i * 32;
        outp[(row0 + w) * HD + c] = (vals[i] - mu) * rstd * lnw[c] + lnb[c];
    }
}

// ---------------- launch ------------------------------------------------------
extern "C" void kernel_launch(void* const* d_in, const int* in_sizes, int n_in,
                              void* d_out, int out_size) {
    const float* x     = (const float*)d_in[0];
    const int*   start = (const int*)  d_in[3];
    const int*   done  = (const int*)  d_in[4];
    const float* Wk    = (const float*)d_in[5];
    const float* Wq    = (const float*)d_in[6];
    const float* Wv    = (const float*)d_in[7];
    const float* Wsk   = (const float*)d_in[8];
    const float* bsk   = (const float*)d_in[9];
    const float* W1    = (const float*)d_in[10];
    const float* b1    = (const float*)d_in[11];
    const float* W2    = (const float*)d_in[12];
    const float* b2    = (const float*)d_in[13];
    const float* W3    = (const float*)d_in[14];
    const float* b3    = (const float*)d_in[15];
    const float* lnw   = (const float*)d_in[16];
    const float* lnb   = (const float*)d_in[17];

    cudaFuncSetAttribute(scan_kernel, cudaFuncAttributeMaxDynamicSharedMemorySize,
                         SCAN_SMEM);

    proj_kernel<<<dim3(NR, NH, 4), 256>>>(x, Wk, Wq, Wv, Wsk, bsk);
    scan_kernel<<<1, 1024, SCAN_SMEM>>>(start, done);
    attn_kernel<<<dim3(NT, NR), 256>>>();
    av_kernel<<<dim3(NR, NH), 256>>>();
    mlp_kernel<<<128, 256>>>(W1, b1, W2, b2, W3, b3, lnw, lnb, (float*)d_out);
}

// round 14
// speedup vs baseline: 1.7521x; 1.7521x over previous
#include <cuda_runtime.h>
#include <math.h>
#include <stdint.h>

#define T  1024
#define HD 256
#define NT (T/64)    // 16 row tiles of 64 (mask granularity)
#define NR 32        // 32 row tiles of 32 (gemm granularity)
#define NH (HD/64)   // 4 col tiles

#define ACT_NONE 0
#define ACT_ELU  1
#define ACT_MISH 2

#define BUF_OUT  4
#define BUF_H1   5
#define BUF_H2   6
#define BUF_H3   7

#define NW   33      // 1025 bits per weight bitset

// ---------------- scratch (static device arrays, allowed) ---------------------
__device__ float    g_k[T*HD];
__device__ float    g_q[T*HD];
__device__ float    g_v[T*HD];
__device__ float    g_skip[T*HD];
__device__ float    g_out[T*HD];
__device__ float    g_h1[T*HD];
__device__ float    g_h2[T*HD];
__device__ float    g_h3[T*HD];
__device__ float    g_attn[T*T];
__device__ uint32_t g_res[1056*NW];     // rows 1..1024 used (final scan bitsets)
__device__ uint32_t g_tileact[NT];
__device__ float    g_kpart[4*T];       // per-coltile partial rowsums of k
__device__ float    g_qpart[4*T];       // per-coltile partial rowsums of q
__device__ float    g_invden[T];

template<int ID> __device__ __forceinline__ float* buf_ptr() {
    if (ID == BUF_OUT)  return g_out;
    if (ID == BUF_H1)   return g_h1;
    if (ID == BUF_H2)   return g_h2;
    return g_h3;
}

// ==== exact jax.lax.associative_scan emulation, smem up-sweep + reg walk-down ==
#define SCAN_SMEM (1023*NW*4)
__global__ __launch_bounds__(1024) void scan_kernel(const int* __restrict__ start,
                                                    const int* __restrict__ done) {
    extern __shared__ uint32_t s_nodes[];
    const int tid = threadIdx.x;

    // level 1: 512 nodes from leaf pairs (2i, 2i+1); leaves are basis vectors
    for (int i = tid; i < 512; i += 1024) {
        uint32_t* o = &s_nodes[i * NW];
        int gb = 2*i + 1;
        bool sm = start[gb] != 0, dm = done[gb] != 0;
        #pragma unroll
        for (int wd = 0; wd < NW; wd++) o[wd] = 0;
        if (sm) o[(2*i) >> 5] |= 1u << ((2*i) & 31);
        if (dm) o[gb >> 5]    |= 1u << (gb & 31);
    }
    __syncthreads();

    // levels 2..10
    for (int d = 2; d <= 10; d++) {
        int nd   = 1024 >> d;
        int offc = 1024 - (2048 >> (d-1));
        int offo = 1024 - (2048 >> d);
        for (int i = tid; i < nd; i += 1024) {
            const uint32_t* a = &s_nodes[(offc + 2*i    ) * NW];
            const uint32_t* b = &s_nodes[(offc + 2*i + 1) * NW];
            int gb = ((2*i + 2) << (d-1)) - 1;
            uint32_t sm = start[gb] ? 0xFFFFFFFFu : 0u;
            uint32_t dm = done[gb]  ? 0xFFFFFFFFu : 0u;
            uint32_t* o = &s_nodes[(offo + i) * NW];
            #pragma unroll
            for (int wd = 0; wd < NW; wd++) o[wd] = (a[wd] & sm) | (b[wd] & dm);
        }
        __syncthreads();
    }

    // per-thread walk-down for row p = tid+1
    const int p = tid + 1;
    uint32_t acc[NW];
    int pushD[11], pushJ[11];
    int np = 0, d = 0, j = p;
    while (j != 0) {
        if (j & 1) { j = (j - 1) >> 1; d++; }
        else       { pushD[np] = d; pushJ[np] = j; np++; j = (j >> 1) - 1; d++; }
    }
    {
        int offb = 1024 - (2048 >> d);
        const uint32_t* b = &s_nodes[offb * NW];
        #pragma unroll
        for (int wd = 0; wd < NW; wd++) acc[wd] = b[wd];
    }
    for (int i = np - 1; i >= 0; i--) {
        int dd = pushD[i], jj = pushJ[i];
        int gb = (dd == 0) ? jj : (((jj + 1) << dd) - 1);
        uint32_t sm = start[gb] ? 0xFFFFFFFFu : 0u;
        uint32_t dm = done[gb]  ? 0xFFFFFFFFu : 0u;
        if (dd == 0) {                       // node = basis(jj)
            #pragma unroll
            for (int wd = 0; wd < NW; wd++) acc[wd] &= sm;
            if (dm) acc[jj >> 5] |= 1u << (jj & 31);
        } else {
            int offn = 1024 - (2048 >> dd);
            const uint32_t* b = &s_nodes[(offn + jj) * NW];
            #pragma unroll
            for (int wd = 0; wd < NW; wd++) acc[wd] = (acc[wd] & sm) | (b[wd] & dm);
        }
    }
    #pragma unroll
    for (int wd = 0; wd < NW; wd++) g_res[p * NW + wd] = acc[wd];

    // tileact from in-register row
    __shared__ uint32_t sh_act[NT];
    if (tid < NT) sh_act[tid] = 0;
    __syncthreads();
    uint32_t mybits = 0;
    #pragma unroll
    for (int ct = 0; ct < 16; ct++) {
        uint32_t any = (acc[2*ct] & 0xFFFFFFFEu) | acc[2*ct + 1] | (acc[2*ct + 2] & 1u);
        if (any) mybits |= 1u << ct;
    }
    #pragma unroll
    for (int o = 16; o; o >>= 1) mybits |= __shfl_xor_sync(0xffffffffu, mybits, o);
    if ((tid & 31) == 0) atomicOr(&sh_act[tid >> 6], mybits);
    __syncthreads();
    if (tid < NT) g_tileact[tid] = sh_act[tid];
}

// ====== 32x64 double-buffered GEMM core =======================================
#define DB_GEMM(AEXPR, BEXPR)                                                  \
    {                                                                          \
        {   int k0 = 0;                                                        \
            _Pragma("unroll")                                                  \
            for (int l = 0; l < 2; l++) { int e = tid + l*256;                 \
                int kk = e & 15, r = e >> 4; As[0][kk][r] = (AEXPR); }         \
            _Pragma("unroll")                                                  \
            for (int l = 0; l < 4; l++) { int e = tid + l*256;                 \
                int kk = e & 15, c = e >> 4; Bs[0][kk][c] = (BEXPR); }         \
        }                                                                      \
        __syncthreads();                                                       \
        _Pragma("unroll")                                                      \
        for (int ch = 0; ch < 16; ch++) {                                      \
            const int cur = ch & 1;                                            \
            float pa[2], pb[4];                                                \
            if (ch < 15) { int k0 = (ch + 1) * 16;                             \
                _Pragma("unroll")                                              \
                for (int l = 0; l < 2; l++) { int e = tid + l*256;             \
                    int kk = e & 15, r = e >> 4; pa[l] = (AEXPR); }            \
                _Pragma("unroll")                                              \
                for (int l = 0; l < 4; l++) { int e = tid + l*256;             \
                    int kk = e & 15, c = e >> 4; pb[l] = (BEXPR); }            \
            }                                                                  \
            _Pragma("unroll")                                                  \
            for (int kk = 0; kk < 16; kk++) {                                  \
                float a0 = As[cur][kk][ty*2], a1 = As[cur][kk][ty*2+1];        \
                float4 b4 = *(const float4*)&Bs[cur][kk][tx*4];                \
                float b[4] = {b4.x, b4.y, b4.z, b4.w};                         \
                _Pragma("unroll")                                              \
                for (int jj = 0; jj < 4; jj++) {                               \
                    acc[0][jj] = fmaf(a0, b[jj], acc[0][jj]);                  \
                    acc[1][jj] = fmaf(a1, b[jj], acc[1][jj]);                  \
                }                                                              \
            }                                                                  \
            if (ch < 15) { const int nxt = cur ^ 1;                            \
                _Pragma("unroll")                                              \
                for (int l = 0; l < 2; l++) { int e = tid + l*256;             \
                    int kk = e & 15, r = e >> 4; As[nxt][kk][r] = pa[l]; }     \
                _Pragma("unroll")                                              \
                for (int l = 0; l < 4; l++) { int e = tid + l*256;             \
                    int kk = e & 15, c = e >> 4; Bs[nxt][kk][c] = pb[l]; }     \
            }                                                                  \
            __syncthreads();                                                   \
        }                                                                      \
    }

// ---- fused QKV+skip projections; k/q also emit per-coltile partial rowsums ---
__global__ __launch_bounds__(256) void proj_kernel(const float* __restrict__ x,
                                                   const float* __restrict__ Wk,
                                                   const float* __restrict__ Wq,
                                                   const float* __restrict__ Wv,
                                                   const float* __restrict__ Wsk,
                                                   const float* __restrict__ bsk) {
    __shared__ float As[2][16][36];
    __shared__ float Bs[2][16][68];
    const int z = blockIdx.z;
    const float* B = (z == 0) ? Wk : (z == 1) ? Wq : (z == 2) ? Wv : Wsk;
    float* C = (z == 0) ? g_k : (z == 1) ? g_q : (z == 2) ? g_v : g_skip;
    const int row0 = blockIdx.x * 32, col0 = blockIdx.y * 64;
    const int tid = threadIdx.x, tx = tid & 15, ty = tid >> 4;
    float acc[2][4] = {};
    DB_GEMM(x[(row0 + r) * HD + k0 + kk], B[(col0 + c) * HD + k0 + kk]);
    float* part = (z == 0) ? g_kpart : g_qpart;
    #pragma unroll
    for (int i = 0; i < 2; i++) {
        int gi = row0 + ty * 2 + i;
        float rs = 0.f;
        #pragma unroll
        for (int j = 0; j < 4; j++) {
            int gj = col0 + tx * 4 + j;
            float v = acc[i][j];
            if (z == 3) v += bsk[gj];
            if (z <= 1) v = v > 0.f ? v : (expf(v) - 1.f);   // ELU for k,q
            C[gi * HD + gj] = v;
            rs += v;
        }
        if (z <= 1) {       // reduce over the 16 tx lanes
            #pragma unroll
            for (int o = 1; o < 16; o <<= 1)
                rs += __shfl_xor_sync(0xffffffffu, rs, o);
            if (tx == 0) part[blockIdx.y * T + gi] = rs;
        }
    }
}

// ---- masked score tiles (32 rows x 64 cols); ct==0 blocks also emit invden ---
__global__ __launch_bounds__(256) void attn_kernel() {
    const int ct = blockIdx.x, rt32 = blockIdx.y;
    const int row0 = rt32 * 32, col0 = ct * 64;
    const int tid = threadIdx.x, tx = tid & 15, ty = tid >> 4;

    // denom for this 32-row strip (runs BEFORE the early-exit; ct==0 only)
    if (ct == 0) {
        const int w = tid >> 5, lane = tid & 31;
        #pragma unroll
        for (int rr = 0; rr < 4; rr++) {
            int r = w + rr * 8;
            const uint32_t* wrow = &g_res[(row0 + r + 1) * NW];
            float zs = 0.f;
            for (int wd = lane; wd < NW; wd += 32) {
                uint32_t word = wrow[wd];
                if (wd == 0) word &= 0xFFFFFFFEu;   // leaf 0 = zeros
                while (word) {
                    int b = __ffs(word) - 1;
                    word &= word - 1;
                    int u = wd * 32 + b - 1;
                    zs += g_kpart[u] + g_kpart[T + u] + g_kpart[2*T + u] + g_kpart[3*T + u];
                }
            }
            #pragma unroll
            for (int o = 16; o; o >>= 1) zs += __shfl_xor_sync(0xffffffffu, zs, o);
            if (lane == 0) {
                int gr = row0 + r;
                float qs = g_qpart[gr] + g_qpart[T + gr] + g_qpart[2*T + gr] + g_qpart[3*T + gr];
                g_invden[gr] = 1.f / fmaxf(qs * zs, 1e-5f);
            }
        }
    }

    if (!((g_tileact[rt32 >> 1] >> ct) & 1)) return;
    __shared__ float As[2][16][36];
    __shared__ float Bs[2][16][68];
    float acc[2][4] = {};
    DB_GEMM(g_q[(row0 + r) * HD + k0 + kk], g_k[(col0 + c) * HD + k0 + kk]);
    #pragma unroll
    for (int i = 0; i < 2; i++) {
        int gi = row0 + ty * 2 + i;
        const uint32_t* wrow = &g_res[(gi + 1) * NW];
        #pragma unroll
        for (int j = 0; j < 4; j++) {
            int pos = col0 + tx * 4 + j + 1;     // leaf index u+1
            float m = ((wrow[pos >> 5] >> (pos & 31)) & 1u) ? 1.f : 0.f;
            g_attn[gi * T + pos - 1] = acc[i][j] * m;
        }
    }
}

// ------- numer = scores @ V; out = numer * invden (32 rows x 64 cols) ---------
__global__ __launch_bounds__(256) void av_kernel() {
    __shared__ float As[16][36];
    __shared__ float Bs[16][68];
    const int rt32 = blockIdx.x, row0 = rt32 * 32, col0 = blockIdx.y * 64;
    const int tid = threadIdx.x, tx = tid & 15, ty = tid >> 4;
    const uint32_t act = g_tileact[rt32 >> 1];
    float acc[2][4] = {};
    for (int ut = 0; ut < NT; ut++) {
        if (!((act >> ut) & 1)) continue;
        const int u0 = ut * 64;
        for (int us = 0; us < 64; us += 16) {
            #pragma unroll
            for (int l = 0; l < 2; l++) {
                int e = tid + l * 256;
                int kk = e & 15, r = e >> 4;
                As[kk][r] = g_attn[(row0 + r) * T + u0 + us + kk];
            }
            #pragma unroll
            for (int l = 0; l < 4; l++) {
                int e = tid + l * 256;
                int kk = e & 15, c = e >> 4;
                Bs[kk][c] = g_v[(u0 + us + kk) * HD + col0 + c];
            }
            __syncthreads();
            #pragma unroll
            for (int kk = 0; kk < 16; kk++) {
                float a0 = As[kk][ty * 2], a1 = As[kk][ty * 2 + 1];
                float4 b4 = *(const float4*)&Bs[kk][tx * 4];
                float b[4] = {b4.x, b4.y, b4.z, b4.w};
                #pragma unroll
                for (int j = 0; j < 4; j++) {
                    acc[0][j] = fmaf(a0, b[j], acc[0][j]);
                    acc[1][j] = fmaf(a1, b[j], acc[1][j]);
                }
            }
            __syncthreads();
        }
    }
    #pragma unroll
    for (int i = 0; i < 2; i++) {
        int gi = row0 + ty * 2 + i;
        float inv = g_invden[gi];
        #pragma unroll
        for (int j = 0; j < 4; j++)
            g_out[gi * HD + col0 + tx * 4 + j] = acc[i][j] * inv;
    }
}

// ---- generic 32x64 GEMM: DST = act(SRC @ B^T + bias [+ g_skip]) --------------
template<int ACT, int SRC, int DST, bool ADDSKIP>
__global__ __launch_bounds__(256) void gemm_kernel(const float* __restrict__ B,
                                                   const float* __restrict__ bias) {
    const float* A = buf_ptr<SRC>();
    float*       C = buf_ptr<DST>();
    __shared__ float As[2][16][36];
    __shared__ float Bs[2][16][68];
    const int row0 = blockIdx.x * 32, col0 = blockIdx.y * 64;
    const int tid = threadIdx.x, tx = tid & 15, ty = tid >> 4;
    float acc[2][4] = {};
    DB_GEMM(A[(row0 + r) * HD + k0 + kk], B[(col0 + c) * HD + k0 + kk]);
    #pragma unroll
    for (int i = 0; i < 2; i++) {
        int gi = row0 + ty * 2 + i;
        #pragma unroll
        for (int j = 0; j < 4; j++) {
            int gj = col0 + tx * 4 + j;
            float v = acc[i][j];
            if (bias)    v += bias[gj];
            if (ADDSKIP) v += g_skip[gi * HD + gj];
            if (ACT == ACT_ELU)  v = v > 0.f ? v : (expf(v) - 1.f);
            if (ACT == ACT_MISH) {
                float sp = v > 20.f ? v : log1pf(expf(v));
                v = v * tanhf(sp);
            }
            C[gi * HD + gj] = v;
        }
    }
}

// ---------------- layernorm over last dim -------------------------------------
__global__ __launch_bounds__(256) void ln_kernel(const float* __restrict__ lnw,
                                                 const float* __restrict__ lnb,
                                                 float* __restrict__ out) {
    const int row = blockIdx.x, t = threadIdx.x;
    __shared__ float red[8];
    float x = g_h3[row * HD + t];
    float s = x;
    #pragma unroll
    for (int o = 16; o; o >>= 1) s += __shfl_xor_sync(0xffffffffu, s, o);
    if ((t & 31) == 0) red[t >> 5] = s;
    __syncthreads();
    float mu = 0.f;
    #pragma unroll
    for (int w = 0; w < 8; w++) mu += red[w];
    mu *= (1.f / HD);
    __syncthreads();
    float d = x - mu;
    float sq = d * d;
    #pragma unroll
    for (int o = 16; o; o >>= 1) sq += __shfl_xor_sync(0xffffffffu, sq, o);
    if ((t & 31) == 0) red[t >> 5] = sq;
    __syncthreads();
    float var = 0.f;
    #pragma unroll
    for (int w = 0; w < 8; w++) var += red[w];
    var *= (1.f / HD);
    out[row * HD + t] = d * rsqrtf(var + 1e-5f) * lnw[t] + lnb[t];
}

// ---------------- launch ------------------------------------------------------
extern "C" void kernel_launch(void* const* d_in, const int* in_sizes, int n_in,
                              void* d_out, int out_size) {
    const float* x     = (const float*)d_in[0];
    const int*   start = (const int*)  d_in[3];
    const int*   done  = (const int*)  d_in[4];
    const float* Wk    = (const float*)d_in[5];
    const float* Wq    = (const float*)d_in[6];
    const float* Wv    = (const float*)d_in[7];
    const float* Wsk   = (const float*)d_in[8];
    const float* bsk   = (const float*)d_in[9];
    const float* W1    = (const float*)d_in[10];
    const float* b1    = (const float*)d_in[11];
    const float* W2    = (const float*)d_in[12];
    const float* b2    = (const float*)d_in[13];
    const float* W3    = (const float*)d_in[14];
    const float* b3    = (const float*)d_in[15];
    const float* lnw   = (const float*)d_in[16];
    const float* lnb   = (const float*)d_in[17];

    cudaFuncSetAttribute(scan_kernel, cudaFuncAttributeMaxDynamicSharedMemorySize,
                         SCAN_SMEM);

    scan_kernel<<<1, 1024, SCAN_SMEM>>>(start, done);
    proj_kernel<<<dim3(NR, NH, 4), 256>>>(x, Wk, Wq, Wv, Wsk, bsk);
    attn_kernel<<<dim3(NT, NR), 256>>>();
    av_kernel<<<dim3(NR, NH), 256>>>();

    dim3 gp(NR, NH);
    gemm_kernel<ACT_MISH, BUF_OUT, BUF_H1, false><<<gp, 256>>>(W1, b1);
    gemm_kernel<ACT_MISH, BUF_H1,  BUF_H2, false><<<gp, 256>>>(W2, b2);
    gemm_kernel<ACT_NONE, BUF_H2,  BUF_H3, true ><<<gp, 256>>>(W3, b3);

    ln_kernel<<<T, 256>>>(lnw, lnb, (float*)d_out);
}